// round 9
// baseline (speedup 1.0000x reference)
#include <cuda_runtime.h>
#include <cstdint>
#include <cmath>

#define H_DIM 1024
#define I_DIM 2816
#define E_NUM 8
#define T_NUM 2048
#define SLOTS (T_NUM * 2)   // 4096 (every token has exactly 2 expert assignments)

// SMEM: 3 stages x (A 128x36 + B 128x36) floats (ring; no same-stage overwrite)
static constexpr int AS_F    = 128 * 36;           // 4608 floats
static constexpr int STAGE_F = 2 * AS_F;           // 9216 floats per stage
static constexpr int N_STAGE = 3;
static constexpr int SMEM_BYTES = N_STAGE * STAGE_F * 4; // 110592 (x2 CTAs = 216KB/SM)

// ---------------- scratch (static __device__, allocation-free) ----------------
__device__ float g_gbuf[SLOTS * I_DIM];   // gate GEMM out
__device__ float g_hbuf[SLOTS * I_DIM];   // h = silu(gate)*up
__device__ int   g_counts[E_NUM];
__device__ int   g_offsets[E_NUM];
__device__ int   g_slot_token[SLOTS];     // slot -> token
__device__ float g_slot_wt[SLOTS];        // slot -> routing weight
__device__ int   g_assign_eid[SLOTS];     // (token,k) -> expert
__device__ float g_assign_wt[SLOTS];      // (token,k) -> weight

__device__ __forceinline__ float to_tf32(float x) {
    float r;
    asm("cvt.rna.tf32.f32 %0, %1;" : "=f"(r) : "f"(x));
    return r;
}
__device__ __forceinline__ uint32_t frag_tf32(float x) {
    return __float_as_uint(to_tf32(x));
}

__device__ __forceinline__ void mma_tf32(float c[4], const uint32_t a[4], const uint32_t b[2]) {
    asm volatile(
        "mma.sync.aligned.m16n8k8.row.col.f32.tf32.tf32.f32 "
        "{%0,%1,%2,%3}, {%4,%5,%6,%7}, {%8,%9}, {%0,%1,%2,%3};\n"
        : "+f"(c[0]), "+f"(c[1]), "+f"(c[2]), "+f"(c[3])
        : "r"(a[0]), "r"(a[1]), "r"(a[2]), "r"(a[3]), "r"(b[0]), "r"(b[1]));
}

__device__ __forceinline__ float silu_f(float g) {
    return g / (1.f + expf(-g));
}

__device__ __forceinline__ uint32_t smem_u32(const void* p) {
    uint32_t a;
    asm("{ .reg .u64 t; cvta.to.shared.u64 t, %1; cvt.u32.u64 %0, t; }" : "=r"(a) : "l"(p));
    return a;
}
#define CP_ASYNC16(dst, src) \
    asm volatile("cp.async.cg.shared.global [%0], [%1], 16;" :: "r"(dst), "l"(src) : "memory")
#define CP_COMMIT() asm volatile("cp.async.commit_group;" ::: "memory")
#define CP_WAIT1()  asm volatile("cp.async.wait_group 1;" ::: "memory")

// ---------------- routing ----------------
__global__ void router_kernel(const float* __restrict__ x, const float* __restrict__ rw) {
    __shared__ float s_rw[E_NUM * H_DIM];  // 32 KB
    int tid = threadIdx.x;
    for (int i = tid; i < E_NUM * H_DIM; i += blockDim.x) s_rw[i] = rw[i];
    __syncthreads();
    int wid = tid >> 5, lane = tid & 31;
    int t = blockIdx.x * 8 + wid;
    const float* xr = x + (size_t)t * H_DIM;
    float acc[E_NUM];
#pragma unroll
    for (int e = 0; e < E_NUM; e++) acc[e] = 0.f;
    for (int h = lane; h < H_DIM; h += 32) {
        float xv = xr[h];
#pragma unroll
        for (int e = 0; e < E_NUM; e++) acc[e] += xv * s_rw[e * H_DIM + h];
    }
#pragma unroll
    for (int e = 0; e < E_NUM; e++) {
#pragma unroll
        for (int o = 16; o > 0; o >>= 1) acc[e] += __shfl_xor_sync(0xffffffff, acc[e], o);
    }
    if (lane == 0) {
        float m = acc[0];
#pragma unroll
        for (int e = 1; e < E_NUM; e++) m = fmaxf(m, acc[e]);
        float p[E_NUM], s = 0.f;
#pragma unroll
        for (int e = 0; e < E_NUM; e++) { p[e] = expf(acc[e] - m); s += p[e]; }
        float inv = 1.f / s;
        int i0 = 0; float v0 = p[0];
#pragma unroll
        for (int e = 1; e < E_NUM; e++) if (p[e] > v0) { v0 = p[e]; i0 = e; }
        int i1 = -1; float v1 = -1.f;
#pragma unroll
        for (int e = 0; e < E_NUM; e++) if (e != i0 && p[e] > v1) { v1 = p[e]; i1 = e; }
        g_assign_eid[t * 2 + 0] = i0;
        g_assign_eid[t * 2 + 1] = i1;
        g_assign_wt[t * 2 + 0] = v0 * inv;
        g_assign_wt[t * 2 + 1] = v1 * inv;
    }
}

// single block: count + scan + scatter
__global__ void bucket_kernel() {
    __shared__ int s_cnt[E_NUM], s_fill[E_NUM];
    int tid = threadIdx.x;
    if (tid < E_NUM) s_cnt[tid] = 0;
    __syncthreads();
    for (int i = tid; i < SLOTS; i += blockDim.x)
        atomicAdd(&s_cnt[g_assign_eid[i]], 1);
    __syncthreads();
    if (tid == 0) {
        int off = 0;
        for (int e = 0; e < E_NUM; e++) {
            g_offsets[e] = off;
            g_counts[e] = s_cnt[e];
            s_fill[e] = off;
            off += s_cnt[e];
        }
    }
    __syncthreads();
    for (int i = tid; i < SLOTS; i += blockDim.x) {
        int e = g_assign_eid[i];
        int slot = atomicAdd(&s_fill[e], 1);
        g_slot_token[slot] = i >> 1;
        g_slot_wt[slot] = g_assign_wt[i];
    }
}

__global__ void zero_out_kernel(float* __restrict__ out) {
    int i = blockIdx.x * blockDim.x + threadIdx.x;
    if (i < T_NUM * H_DIM / 4) ((float4*)out)[i] = make_float4(0.f, 0.f, 0.f, 0.f);
}

// ------ grouped TN GEMM, tf32 mma, cp.async 3-stage ring, 2 CTAs/SM ------
// C[m,n] = sum_k A[m,k] * B[e][n,k]
// MODE 0: gate  (A = x gathered via slot_token) -> g_gbuf
// MODE 1: up    (A = x gathered)  epilogue h = silu(g_gbuf)*u -> g_hbuf
// MODE 2: down  (A = g_hbuf slot rows) epilogue out[token] += w * y (atomic)
template <int KDIM, int MODE>
__global__ __launch_bounds__(256, 2)
void gemm_tn_kernel(const float* __restrict__ X,
                    const float* __restrict__ Bfull,
                    float* __restrict__ OUT,
                    int NDIM) {
    extern __shared__ float smf[];

    const float* A = (MODE == 2) ? (const float*)g_hbuf : X;

    const int e   = blockIdx.z;
    const int cnt = g_counts[e];
    const int off = g_offsets[e];
    const int m0  = blockIdx.x * 128;
    if (m0 >= cnt) return;
    const int n0  = blockIdx.y * 128;

    const int tid  = threadIdx.x;
    const int wid  = tid >> 5;
    const int lane = tid & 31;
    const int wm   = wid >> 2;   // 0..1 (64 rows each)
    const int wn   = wid & 3;    // 0..3 (32 cols each)
    const int g    = lane >> 2;  // 0..7
    const int tig  = lane & 3;   // 0..3

    const float* Bw = Bfull + (size_t)e * NDIM * KDIM + (size_t)n0 * KDIM;

    // staging mapping: each thread copies 4 A rows + 4 B rows, 16B each, per tile
    const int r_st  = tid >> 3;        // 0..31 (row within 32-row group)
    const int kc_st = (tid & 7) * 4;   // 0,4,...,28
    const float* abase[4];
    const float* bbase[4];
#pragma unroll
    for (int i = 0; i < 4; i++) {
        int r = r_st + i * 32;
        int mi = m0 + r;
        int grow;
        if (MODE != 2) {
            grow = g_slot_token[off + ((mi < cnt) ? mi : (cnt - 1))];
        } else {
            grow = off + ((mi < cnt) ? mi : (cnt - 1));
        }
        abase[i] = A + (size_t)grow * KDIM + kc_st;
        bbase[i] = Bw + (size_t)r * KDIM + kc_st;
    }

    const uint32_t sm0 = smem_u32(smf);
    uint32_t dstA[4], dstB[4];
#pragma unroll
    for (int i = 0; i < 4; i++) {
        dstA[i] = (uint32_t)(((r_st + i * 32) * 36 + kc_st) * 4);
        dstB[i] = dstA[i] + (uint32_t)(AS_F * 4);
    }

    auto issue_tile = [&](int kt) {
        const uint32_t st = sm0 + (uint32_t)((kt % N_STAGE) * STAGE_F * 4);
        const int ko = kt * 32;
#pragma unroll
        for (int i = 0; i < 4; i++) CP_ASYNC16(st + dstA[i], abase[i] + ko);
#pragma unroll
        for (int i = 0; i < 4; i++) CP_ASYNC16(st + dstB[i], bbase[i] + ko);
    };

    float c[4][4][4];
#pragma unroll
    for (int mt = 0; mt < 4; mt++)
#pragma unroll
        for (int nt = 0; nt < 4; nt++)
#pragma unroll
            for (int j = 0; j < 4; j++) c[mt][nt][j] = 0.f;

    constexpr int KT = KDIM / 32;
    issue_tile(0); CP_COMMIT();
    issue_tile(1); CP_COMMIT();

    for (int kt = 0; kt < KT; kt++) {
        CP_WAIT1();          // own copies of tile kt landed
        __syncthreads();     // all threads' tile-kt copies visible; also proves every
                             // warp finished mma(kt-1), so stage (kt+2)%3 is free
        if (kt + 2 < KT) issue_tile(kt + 2);   // ring stage (kt+2)%3 — NOT the one read now
        CP_COMMIT();         // (possibly empty) group keeps the pending count in step

        const float* sA = smf + (kt % N_STAGE) * STAGE_F;
        const float* sB = sA + AS_F;
#pragma unroll
        for (int ks = 0; ks < 4; ks++) {
            int kk = ks * 8;
            uint32_t af[4][4], bf[4][2];
#pragma unroll
            for (int mt = 0; mt < 4; mt++) {
                int m = wm * 64 + mt * 16;
                af[mt][0] = frag_tf32(sA[(m + g) * 36 + kk + tig]);
                af[mt][1] = frag_tf32(sA[(m + g + 8) * 36 + kk + tig]);
                af[mt][2] = frag_tf32(sA[(m + g) * 36 + kk + tig + 4]);
                af[mt][3] = frag_tf32(sA[(m + g + 8) * 36 + kk + tig + 4]);
            }
#pragma unroll
            for (int nt = 0; nt < 4; nt++) {
                int n = wn * 32 + nt * 8;
                bf[nt][0] = frag_tf32(sB[(n + g) * 36 + kk + tig]);
                bf[nt][1] = frag_tf32(sB[(n + g) * 36 + kk + tig + 4]);
            }
#pragma unroll
            for (int mt = 0; mt < 4; mt++)
#pragma unroll
                for (int nt = 0; nt < 4; nt++)
                    mma_tf32(c[mt][nt], af[mt], bf[nt]);
        }
    }

    // ---------------- epilogue ----------------
    const int cntloc = cnt - m0;
#pragma unroll
    for (int mt = 0; mt < 4; mt++) {
        const int r_lo = wm * 64 + mt * 16 + g;
        const int r_hi = r_lo + 8;
        const bool v_lo = r_lo < cntloc;
        const bool v_hi = r_hi < cntloc;

        if (MODE == 2) {
            int slot_lo = off + m0 + (v_lo ? r_lo : 0);
            int slot_hi = off + m0 + (v_hi ? r_hi : 0);
            int   tok_lo = g_slot_token[slot_lo];
            int   tok_hi = g_slot_token[slot_hi];
            float w_lo   = g_slot_wt[slot_lo];
            float w_hi   = g_slot_wt[slot_hi];
#pragma unroll
            for (int nt = 0; nt < 4; nt++) {
                int col = n0 + wn * 32 + nt * 8 + 2 * tig;
                if (v_lo) {
                    float* p = OUT + (size_t)tok_lo * H_DIM + col;
                    atomicAdd(p + 0, w_lo * c[mt][nt][0]);
                    atomicAdd(p + 1, w_lo * c[mt][nt][1]);
                }
                if (v_hi) {
                    float* p = OUT + (size_t)tok_hi * H_DIM + col;
                    atomicAdd(p + 0, w_hi * c[mt][nt][2]);
                    atomicAdd(p + 1, w_hi * c[mt][nt][3]);
                }
            }
        } else {
#pragma unroll
            for (int nt = 0; nt < 4; nt++) {
                int col = n0 + wn * 32 + nt * 8 + 2 * tig;
                size_t idx_lo = (size_t)(off + m0 + r_lo) * I_DIM + col;
                size_t idx_hi = (size_t)(off + m0 + r_hi) * I_DIM + col;
                if (MODE == 0) {
                    if (v_lo) {
                        g_gbuf[idx_lo + 0] = c[mt][nt][0];
                        g_gbuf[idx_lo + 1] = c[mt][nt][1];
                    }
                    if (v_hi) {
                        g_gbuf[idx_hi + 0] = c[mt][nt][2];
                        g_gbuf[idx_hi + 1] = c[mt][nt][3];
                    }
                } else {  // MODE 1: h = silu(g) * u
                    if (v_lo) {
                        float2 gv = *(const float2*)(g_gbuf + idx_lo);
                        float2 h;
                        h.x = silu_f(gv.x) * c[mt][nt][0];
                        h.y = silu_f(gv.y) * c[mt][nt][1];
                        *(float2*)(g_hbuf + idx_lo) = h;
                    }
                    if (v_hi) {
                        float2 gv = *(const float2*)(g_gbuf + idx_hi);
                        float2 h;
                        h.x = silu_f(gv.x) * c[mt][nt][2];
                        h.y = silu_f(gv.y) * c[mt][nt][3];
                        *(float2*)(g_hbuf + idx_hi) = h;
                    }
                }
            }
        }
    }
}

// ---------------- launch ----------------
extern "C" void kernel_launch(void* const* d_in, const int* in_sizes, int n_in,
                              void* d_out, int out_size) {
    const float* x  = (const float*)d_in[0];   // [2048,1024]
    const float* rw = (const float*)d_in[1];   // [8,1024]
    const float* gw = (const float*)d_in[2];   // [8,2816,1024]
    const float* uw = (const float*)d_in[3];   // [8,2816,1024]
    const float* dw = (const float*)d_in[4];   // [8,1024,2816]
    float* out = (float*)d_out;                // [2048,1024]

    cudaFuncSetAttribute(gemm_tn_kernel<H_DIM, 0>,
                         cudaFuncAttributeMaxDynamicSharedMemorySize, SMEM_BYTES);
    cudaFuncSetAttribute(gemm_tn_kernel<H_DIM, 1>,
                         cudaFuncAttributeMaxDynamicSharedMemorySize, SMEM_BYTES);
    cudaFuncSetAttribute(gemm_tn_kernel<I_DIM, 2>,
                         cudaFuncAttributeMaxDynamicSharedMemorySize, SMEM_BYTES);

    router_kernel<<<T_NUM / 8, 256>>>(x, rw);
    bucket_kernel<<<1, 512>>>();
    zero_out_kernel<<<(T_NUM * H_DIM / 4 + 255) / 256, 256>>>(out);

    // gate: [slots] x [I] = x @ gate_w^T
    gemm_tn_kernel<H_DIM, 0><<<dim3(SLOTS / 128, I_DIM / 128, E_NUM), 256, SMEM_BYTES>>>(
        x, gw, nullptr, I_DIM);
    // up + fused silu: h = silu(g) * (x @ up_w^T)
    gemm_tn_kernel<H_DIM, 1><<<dim3(SLOTS / 128, I_DIM / 128, E_NUM), 256, SMEM_BYTES>>>(
        x, uw, nullptr, I_DIM);
    // down + fused weighted combine
    gemm_tn_kernel<I_DIM, 2><<<dim3(SLOTS / 128, H_DIM / 128, E_NUM), 256, SMEM_BYTES>>>(
        nullptr, dw, out, H_DIM);
}

// round 10
// speedup vs baseline: 1.4347x; 1.4347x over previous
#include <cuda_runtime.h>
#include <cuda_fp16.h>
#include <cstdint>
#include <cmath>

#define H_DIM 1024
#define I_DIM 2816
#define E_NUM 8
#define T_NUM 2048
#define SLOTS (T_NUM * 2)   // 4096 (every token has exactly 2 expert assignments)

// SMEM (half): 2 stages x (A 128x40 + B 128x40) halfs, pitch 40 for bank-conflict-free frags
static constexpr int PH       = 40;                 // row pitch in halfs (80 B)
static constexpr int AS_H     = 128 * PH;           // 5120 halfs per operand
static constexpr int STAGE_H  = 2 * AS_H;           // 10240 halfs per stage
static constexpr int SMEM_BYTES = 2 * STAGE_H * 2;  // 40960 B (x2 CTAs = 80KB/SM)

// ---------------- scratch (static __device__, allocation-free) ----------------
__device__ float g_gbuf[SLOTS * I_DIM];   // gate GEMM out
__device__ float g_hbuf[SLOTS * I_DIM];   // h = silu(gate)*up
__device__ int   g_counts[E_NUM];
__device__ int   g_offsets[E_NUM];
__device__ int   g_slot_token[SLOTS];     // slot -> token
__device__ float g_slot_wt[SLOTS];        // slot -> routing weight
__device__ int   g_assign_eid[SLOTS];     // (token,k) -> expert
__device__ float g_assign_wt[SLOTS];      // (token,k) -> weight

__device__ __forceinline__ void mma_f16(float c[4], const uint32_t a[4], const uint32_t b[2]) {
    asm volatile(
        "mma.sync.aligned.m16n8k16.row.col.f32.f16.f16.f32 "
        "{%0,%1,%2,%3}, {%4,%5,%6,%7}, {%8,%9}, {%0,%1,%2,%3};\n"
        : "+f"(c[0]), "+f"(c[1]), "+f"(c[2]), "+f"(c[3])
        : "r"(a[0]), "r"(a[1]), "r"(a[2]), "r"(a[3]), "r"(b[0]), "r"(b[1]));
}

__device__ __forceinline__ float silu_f(float g) {
    return g / (1.f + expf(-g));
}

__device__ __forceinline__ uint2 pack4(float4 v) {
    __half2 lo = __floats2half2_rn(v.x, v.y);
    __half2 hi = __floats2half2_rn(v.z, v.w);
    uint2 r;
    r.x = *(uint32_t*)&lo;
    r.y = *(uint32_t*)&hi;
    return r;
}

// ---------------- routing ----------------
__global__ void router_kernel(const float* __restrict__ x, const float* __restrict__ rw) {
    __shared__ float s_rw[E_NUM * H_DIM];  // 32 KB
    int tid = threadIdx.x;
    for (int i = tid; i < E_NUM * H_DIM; i += blockDim.x) s_rw[i] = rw[i];
    __syncthreads();
    int wid = tid >> 5, lane = tid & 31;
    int t = blockIdx.x * 8 + wid;
    const float* xr = x + (size_t)t * H_DIM;
    float acc[E_NUM];
#pragma unroll
    for (int e = 0; e < E_NUM; e++) acc[e] = 0.f;
    for (int h = lane; h < H_DIM; h += 32) {
        float xv = xr[h];
#pragma unroll
        for (int e = 0; e < E_NUM; e++) acc[e] += xv * s_rw[e * H_DIM + h];
    }
#pragma unroll
    for (int e = 0; e < E_NUM; e++) {
#pragma unroll
        for (int o = 16; o > 0; o >>= 1) acc[e] += __shfl_xor_sync(0xffffffff, acc[e], o);
    }
    if (lane == 0) {
        float m = acc[0];
#pragma unroll
        for (int e = 1; e < E_NUM; e++) m = fmaxf(m, acc[e]);
        float p[E_NUM], s = 0.f;
#pragma unroll
        for (int e = 0; e < E_NUM; e++) { p[e] = expf(acc[e] - m); s += p[e]; }
        float inv = 1.f / s;
        int i0 = 0; float v0 = p[0];
#pragma unroll
        for (int e = 1; e < E_NUM; e++) if (p[e] > v0) { v0 = p[e]; i0 = e; }
        int i1 = -1; float v1 = -1.f;
#pragma unroll
        for (int e = 0; e < E_NUM; e++) if (e != i0 && p[e] > v1) { v1 = p[e]; i1 = e; }
        g_assign_eid[t * 2 + 0] = i0;
        g_assign_eid[t * 2 + 1] = i1;
        g_assign_wt[t * 2 + 0] = v0 * inv;
        g_assign_wt[t * 2 + 1] = v1 * inv;
    }
}

// single block: count + scan + scatter
__global__ void bucket_kernel() {
    __shared__ int s_cnt[E_NUM], s_fill[E_NUM];
    int tid = threadIdx.x;
    if (tid < E_NUM) s_cnt[tid] = 0;
    __syncthreads();
    for (int i = tid; i < SLOTS; i += blockDim.x)
        atomicAdd(&s_cnt[g_assign_eid[i]], 1);
    __syncthreads();
    if (tid == 0) {
        int off = 0;
        for (int e = 0; e < E_NUM; e++) {
            g_offsets[e] = off;
            g_counts[e] = s_cnt[e];
            s_fill[e] = off;
            off += s_cnt[e];
        }
    }
    __syncthreads();
    for (int i = tid; i < SLOTS; i += blockDim.x) {
        int e = g_assign_eid[i];
        int slot = atomicAdd(&s_fill[e], 1);
        g_slot_token[slot] = i >> 1;
        g_slot_wt[slot] = g_assign_wt[i];
    }
}

__global__ void zero_out_kernel(float* __restrict__ out) {
    int i = blockIdx.x * blockDim.x + threadIdx.x;
    if (i < T_NUM * H_DIM / 4) ((float4*)out)[i] = make_float4(0.f, 0.f, 0.f, 0.f);
}

// -- grouped TN GEMM, fp16 mma (m16n8k16), double-buffered SMEM, 2 CTAs/SM ----
// C[m,n] = sum_k A[m,k] * B[e][n,k]; fp32 accumulate in tensor core.
// MODE 0: gate  (A = x gathered via slot_token) -> g_gbuf
// MODE 1: up    (A = x gathered)  epilogue h = silu(g_gbuf)*u -> g_hbuf
// MODE 2: down  (A = g_hbuf slot rows) epilogue out[token] += w * y (atomic)
template <int KDIM, int MODE>
__global__ __launch_bounds__(256, 2)
void gemm_tn_kernel(const float* __restrict__ X,
                    const float* __restrict__ Bfull,
                    float* __restrict__ OUT,
                    int NDIM) {
    extern __shared__ __half smh[];

    const float* A = (MODE == 2) ? (const float*)g_hbuf : X;

    const int e   = blockIdx.z;
    const int cnt = g_counts[e];
    const int off = g_offsets[e];
    const int m0  = blockIdx.x * 128;
    if (m0 >= cnt) return;
    const int n0  = blockIdx.y * 128;

    const int tid  = threadIdx.x;
    const int wid  = tid >> 5;
    const int lane = tid & 31;
    const int wm   = wid >> 2;   // 0..1 (64 rows each)
    const int wn   = wid & 3;    // 0..3 (32 cols each)
    const int g    = lane >> 2;  // 0..7
    const int tig  = lane & 3;   // 0..3

    const float* Bw = Bfull + (size_t)e * NDIM * KDIM + (size_t)n0 * KDIM;

    // staging mapping: each thread loads 4 A rows + 4 B rows x float4, converts
    // to half2 pairs, stores 8 B per row slot.
    const int r_st  = tid >> 3;        // 0..31 (row within 32-row group)
    const int kc_st = (tid & 7) * 4;   // 0,4,...,28
    const float* abase[4];
    const float* bbase[4];
#pragma unroll
    for (int i = 0; i < 4; i++) {
        int r = r_st + i * 32;
        int mi = m0 + r;
        int grow;
        if (MODE != 2) {
            grow = g_slot_token[off + ((mi < cnt) ? mi : (cnt - 1))];
        } else {
            grow = off + ((mi < cnt) ? mi : (cnt - 1));
        }
        abase[i] = A + (size_t)grow * KDIM + kc_st;
        bbase[i] = Bw + (size_t)r * KDIM + kc_st;
    }

    float c[4][4][4];
#pragma unroll
    for (int mt = 0; mt < 4; mt++)
#pragma unroll
        for (int nt = 0; nt < 4; nt++)
#pragma unroll
            for (int j = 0; j < 4; j++) c[mt][nt][j] = 0.f;

    constexpr int KT = KDIM / 32;
    for (int kt = 0; kt < KT; kt++) {
        const int s = kt & 1;
        __half* sA = smh + s * STAGE_H;
        __half* sB = sA + AS_H;
        // transient stage: LDG float4 -> cvt f16x2 -> STS.64 (cvt once per value)
        {
            const int ko = kt * 32;
#pragma unroll
            for (int i = 0; i < 4; i++) {
                float4 ra = *(const float4*)(abase[i] + ko);
                *(uint2*)&sA[(r_st + i * 32) * PH + kc_st] = pack4(ra);
            }
#pragma unroll
            for (int i = 0; i < 4; i++) {
                float4 rb = *(const float4*)(bbase[i] + ko);
                *(uint2*)&sB[(r_st + i * 32) * PH + kc_st] = pack4(rb);
            }
        }
        __syncthreads();
        // mma over buffer s: 2 ksteps of k16. Single sync per tile is safe: the
        // re-stage of buffer s at kt+2 happens after sync(kt+1), which every warp
        // reaches only after its mma reads of buffer s at kt.
#pragma unroll
        for (int ks = 0; ks < 2; ks++) {
            const int kk = ks * 16;
            uint32_t af[4][4], bf[4][2];
#pragma unroll
            for (int mt = 0; mt < 4; mt++) {
                int m = wm * 64 + mt * 16;
                const __half* a0 = &sA[(m + g) * PH + kk + 2 * tig];
                const __half* a1 = &sA[(m + g + 8) * PH + kk + 2 * tig];
                af[mt][0] = *(const uint32_t*)(a0);
                af[mt][1] = *(const uint32_t*)(a1);
                af[mt][2] = *(const uint32_t*)(a0 + 8);
                af[mt][3] = *(const uint32_t*)(a1 + 8);
            }
#pragma unroll
            for (int nt = 0; nt < 4; nt++) {
                int n = wn * 32 + nt * 8;
                const __half* b0 = &sB[(n + g) * PH + kk + 2 * tig];
                bf[nt][0] = *(const uint32_t*)(b0);
                bf[nt][1] = *(const uint32_t*)(b0 + 8);
            }
#pragma unroll
            for (int mt = 0; mt < 4; mt++)
#pragma unroll
                for (int nt = 0; nt < 4; nt++)
                    mma_f16(c[mt][nt], af[mt], bf[nt]);
        }
    }

    // ---------------- epilogue (same accumulator layout as m16n8k8) ----------
    const int cntloc = cnt - m0;
#pragma unroll
    for (int mt = 0; mt < 4; mt++) {
        const int r_lo = wm * 64 + mt * 16 + g;
        const int r_hi = r_lo + 8;
        const bool v_lo = r_lo < cntloc;
        const bool v_hi = r_hi < cntloc;

        if (MODE == 2) {
            int slot_lo = off + m0 + (v_lo ? r_lo : 0);
            int slot_hi = off + m0 + (v_hi ? r_hi : 0);
            int   tok_lo = g_slot_token[slot_lo];
            int   tok_hi = g_slot_token[slot_hi];
            float w_lo   = g_slot_wt[slot_lo];
            float w_hi   = g_slot_wt[slot_hi];
#pragma unroll
            for (int nt = 0; nt < 4; nt++) {
                int col = n0 + wn * 32 + nt * 8 + 2 * tig;
                if (v_lo) {
                    float* p = OUT + (size_t)tok_lo * H_DIM + col;
                    atomicAdd(p + 0, w_lo * c[mt][nt][0]);
                    atomicAdd(p + 1, w_lo * c[mt][nt][1]);
                }
                if (v_hi) {
                    float* p = OUT + (size_t)tok_hi * H_DIM + col;
                    atomicAdd(p + 0, w_hi * c[mt][nt][2]);
                    atomicAdd(p + 1, w_hi * c[mt][nt][3]);
                }
            }
        } else {
#pragma unroll
            for (int nt = 0; nt < 4; nt++) {
                int col = n0 + wn * 32 + nt * 8 + 2 * tig;
                size_t idx_lo = (size_t)(off + m0 + r_lo) * I_DIM + col;
                size_t idx_hi = (size_t)(off + m0 + r_hi) * I_DIM + col;
                if (MODE == 0) {
                    if (v_lo) {
                        g_gbuf[idx_lo + 0] = c[mt][nt][0];
                        g_gbuf[idx_lo + 1] = c[mt][nt][1];
                    }
                    if (v_hi) {
                        g_gbuf[idx_hi + 0] = c[mt][nt][2];
                        g_gbuf[idx_hi + 1] = c[mt][nt][3];
                    }
                } else {  // MODE 1: h = silu(g) * u
                    if (v_lo) {
                        float2 gv = *(const float2*)(g_gbuf + idx_lo);
                        float2 h;
                        h.x = silu_f(gv.x) * c[mt][nt][0];
                        h.y = silu_f(gv.y) * c[mt][nt][1];
                        *(float2*)(g_hbuf + idx_lo) = h;
                    }
                    if (v_hi) {
                        float2 gv = *(const float2*)(g_gbuf + idx_hi);
                        float2 h;
                        h.x = silu_f(gv.x) * c[mt][nt][2];
                        h.y = silu_f(gv.y) * c[mt][nt][3];
                        *(float2*)(g_hbuf + idx_hi) = h;
                    }
                }
            }
        }
    }
}

// ---------------- launch ----------------
extern "C" void kernel_launch(void* const* d_in, const int* in_sizes, int n_in,
                              void* d_out, int out_size) {
    const float* x  = (const float*)d_in[0];   // [2048,1024]
    const float* rw = (const float*)d_in[1];   // [8,1024]
    const float* gw = (const float*)d_in[2];   // [8,2816,1024]
    const float* uw = (const float*)d_in[3];   // [8,2816,1024]
    const float* dw = (const float*)d_in[4];   // [8,1024,2816]
    float* out = (float*)d_out;                // [2048,1024]

    cudaFuncSetAttribute(gemm_tn_kernel<H_DIM, 0>,
                         cudaFuncAttributeMaxDynamicSharedMemorySize, SMEM_BYTES);
    cudaFuncSetAttribute(gemm_tn_kernel<H_DIM, 1>,
                         cudaFuncAttributeMaxDynamicSharedMemorySize, SMEM_BYTES);
    cudaFuncSetAttribute(gemm_tn_kernel<I_DIM, 2>,
                         cudaFuncAttributeMaxDynamicSharedMemorySize, SMEM_BYTES);

    router_kernel<<<T_NUM / 8, 256>>>(x, rw);
    bucket_kernel<<<1, 512>>>();
    zero_out_kernel<<<(T_NUM * H_DIM / 4 + 255) / 256, 256>>>(out);

    // gate: [slots] x [I] = x @ gate_w^T
    gemm_tn_kernel<H_DIM, 0><<<dim3(SLOTS / 128, I_DIM / 128, E_NUM), 256, SMEM_BYTES>>>(
        x, gw, nullptr, I_DIM);
    // up + fused silu: h = silu(g) * (x @ up_w^T)
    gemm_tn_kernel<H_DIM, 1><<<dim3(SLOTS / 128, I_DIM / 128, E_NUM), 256, SMEM_BYTES>>>(
        x, uw, nullptr, I_DIM);
    // down + fused weighted combine
    gemm_tn_kernel<I_DIM, 2><<<dim3(SLOTS / 128, H_DIM / 128, E_NUM), 256, SMEM_BYTES>>>(
        nullptr, dw, out, H_DIM);
}